// round 8
// baseline (speedup 1.0000x reference)
#include <cuda_runtime.h>
#include <cstdint>

#define HW_      262144        // 512*512 floats per channel
#define C_       9
#define N_       16
#define NCH_     144           // N_*C_
#define NT_      1024          // threads per CTA
#define SLOTS_   256           // per-thread candidate slots (exact worst case)
#define CHUNK_F4 2048          // 32KB chunk = 2048 float4
#define NCHUNK   32            // 32 chunks per channel
#define STAGES   4

// Scratch (device globals — no allocation allowed)
__device__ unsigned long long g_cand[(size_t)NCH_ * HW_];
// Bitmap (per channel, 8192 words): word[g*1024+t], bit cc*8+h*4+e
//   <-> element f4 = (g*4+cc)*2048 + h*1024 + t, elem e.   g:0..7 cc:0..3 h:0..1
__device__ unsigned g_bitmap[NCH_ * (HW_ / 32)];
__device__ unsigned g_bar_cnt;
__device__ unsigned g_bar_flag;

static __device__ __forceinline__ unsigned f2key(float f) {
    unsigned u = __float_as_uint(f);
    return (u & 0x80000000u) ? ~u : (u | 0x80000000u);
}
static __device__ __forceinline__ unsigned s2u(const void* p) {
    return (unsigned)__cvta_generic_to_shared(p);
}
static __device__ __forceinline__ void mb_init(unsigned a, unsigned cnt) {
    asm volatile("mbarrier.init.shared::cta.b64 [%0], %1;" :: "r"(a), "r"(cnt) : "memory");
}
static __device__ __forceinline__ void mb_expect_tx(unsigned a, unsigned bytes) {
    asm volatile("mbarrier.arrive.expect_tx.shared::cta.b64 _, [%0], %1;"
                 :: "r"(a), "r"(bytes) : "memory");
}
static __device__ __forceinline__ void bulk_g2s(unsigned dst, const void* src,
                                                unsigned bytes, unsigned mbar) {
    asm volatile("cp.async.bulk.shared::cta.global.mbarrier::complete_tx::bytes "
                 "[%0], [%1], %2, [%3];"
                 :: "r"(dst), "l"(src), "r"(bytes), "r"(mbar) : "memory");
}
static __device__ __forceinline__ void mb_wait(unsigned a, unsigned ph) {
    unsigned done;
    do {
        asm volatile("{\n\t.reg .pred p;\n\t"
                     "mbarrier.try_wait.parity.acquire.cta.shared::cta.b64 p, [%1], %2, 0x989680;\n\t"
                     "selp.b32 %0, 1, 0, p;\n\t}"
                     : "=r"(done) : "r"(a), "r"(ph) : "memory");
    } while (!done);
}

// Block-wide "find bin containing rank-from-top" over hist[0..nb), nb in {2048,1024}.
static __device__ __forceinline__ void block_find_bin(
    unsigned* hist, int nb, unsigned rank,
    unsigned* sgrp, unsigned* aux, int tid, int lane, int w)
{
    unsigned s = (nb == 2048) ? (hist[tid * 2] + hist[tid * 2 + 1]) : hist[tid];
    sgrp[tid] = s;
    __syncthreads();
    if (w == 0) {
        unsigned sup = 0;
        #pragma unroll 4
        for (int j = 0; j < 32; j++) sup += sgrp[lane * 32 + j];
        unsigned v = sup;
        #pragma unroll
        for (int off = 1; off < 32; off <<= 1) {
            unsigned t = __shfl_down_sync(0xffffffffu, v, off);
            if (lane + off < 32) v += t;
        }
        unsigned cumAbove = v - sup;
        bool hit = (cumAbove < rank) && (cumAbove + sup >= rank);
        unsigned bal = __ballot_sync(0xffffffffu, hit);
        int Ls = __ffs(bal) - 1;
        if (lane == Ls) {
            unsigned cum = cumAbove;
            for (int g = Ls * 32 + 31; ; g--) {
                unsigned sg = sgrp[g];
                if (cum + sg >= rank) {
                    int B = (nb == 2048) ? 2 : 1;
                    for (int b = g * B + B - 1; ; b--) {
                        unsigned h = hist[b];
                        if (cum + h >= rank) { aux[0] = (unsigned)b; aux[1] = rank - cum; break; }
                        cum += h;
                    }
                    break;
                }
                cum += sg;
            }
        }
    }
    __syncthreads();
}

__global__ void __launch_bounds__(NT_) k_fused(const float* __restrict__ inp,
                                               const float* __restrict__ ratio,
                                               const float* __restrict__ x,
                                               float* __restrict__ out)
{
    extern __shared__ unsigned char smem_raw[];
    float4*   buf  = (float4*)smem_raw;                               // 131072 B
    unsigned* hist = (unsigned*)(smem_raw + STAGES * CHUNK_F4 * 16);  // 2048
    unsigned* sgrp = hist + 2048;                                     // 1024
    unsigned* aux  = sgrp + 1024;                                     // 4
    unsigned long long* mbar = (unsigned long long*)(aux + 4);        // 4, 8B-aligned

    int ch = blockIdx.x, n = ch / C_;
    int tid = threadIdx.x, w = tid >> 5, lane = tid & 31;

    unsigned mb[STAGES];
    #pragma unroll
    for (int s = 0; s < STAGES; s++) mb[s] = s2u(&mbar[s]);
    if (tid == 0) {
        #pragma unroll
        for (int s = 0; s < STAGES; s++) mb_init(mb[s], 1);
        asm volatile("fence.proxy.async.shared::cta;" ::: "memory");
    }
    __syncthreads();

    // k: replicate reference f32 arithmetic exactly
    float f_p = floorf(ratio[n] * 262144.0f);
    int k = (int)floorf(f_p * 0.15f);
    bool k0 = (k <= 0);

    const char* src = (const char*)(inp + (size_t)ch * HW_);
    const float INF = __int_as_float(0x7F800000);

    float lo_f, hi_f;
    if (k0) {
        lo_f = hi_f = 1.0f;            // reference: thr = 1.0 when k == 0 (strict >, exact)
    } else {
        float q = (float)k * (1.0f / 262144.0f);
        float t = sqrtf(-2.0f * logf(q));               // A&S 26.2.23
        float z = t - (2.515517f + 0.802853f * t + 0.010328f * t * t)
                    / (1.0f + 1.432788f * t + 0.189269f * t * t + 0.001308f * t * t * t);
        float phi = 0.3989423f * expf(-0.5f * z * z);
        float delta = 0.008f + 10.0f * sqrtf((float)k) / (262144.0f * phi);
        lo_f = z - delta; hi_f = z + delta;
    }

    unsigned long long* myc = g_cand + (size_t)ch * HW_ + (size_t)tid * SLOTS_;
    unsigned* gbch = g_bitmap + (size_t)ch * 8192;
    unsigned cnt_hi, m;
    int mycap;
    for (int attempt = 0; ; attempt++) {
        if (tid == 0) {
            aux[0] = 0; aux[1] = 0;
            #pragma unroll
            for (int s = 0; s < STAGES; s++) {         // preload stages 0..3
                mb_expect_tx(mb[s], CHUNK_F4 * 16);
                bulk_g2s(s2u(&buf[s * CHUNK_F4]), src + (size_t)s * CHUNK_F4 * 16,
                         CHUNK_F4 * 16, mb[s]);
            }
        }
        __syncthreads();
        unsigned mycnt = 0, word = 0;
        mycap = 0;
        for (int i = 0; i < NCHUNK; i++) {
            int s = i & 3;
            mb_wait(mb[s], (i >> 2) & 1);              // parity resets each pass (8 uses/stage)
            float4 va = buf[s * CHUNK_F4 + tid];
            float4 vb = buf[s * CHUNK_F4 + 1024 + tid];
            unsigned hiA = (unsigned)(va.x > hi_f) | ((unsigned)(va.y > hi_f) << 1)
                         | ((unsigned)(va.z > hi_f) << 2) | ((unsigned)(va.w > hi_f) << 3);
            unsigned loA = (unsigned)(va.x > lo_f) | ((unsigned)(va.y > lo_f) << 1)
                         | ((unsigned)(va.z > lo_f) << 2) | ((unsigned)(va.w > lo_f) << 3);
            unsigned hiB = (unsigned)(vb.x > hi_f) | ((unsigned)(vb.y > hi_f) << 1)
                         | ((unsigned)(vb.z > hi_f) << 2) | ((unsigned)(vb.w > hi_f) << 3);
            unsigned loB = (unsigned)(vb.x > lo_f) | ((unsigned)(vb.y > lo_f) << 1)
                         | ((unsigned)(vb.z > lo_f) << 2) | ((unsigned)(vb.w > lo_f) << 3);
            int cc = i & 3;
            word |= (hiA << (cc * 8)) | (hiB << (cc * 8 + 4));
            unsigned cnA = loA & ~hiA, cnB = loB & ~hiB;
            if (cnA | cnB) {                            // rare (~0.2-2%)
                int fa = i * CHUNK_F4 + tid, fb = fa + 1024;
                if (cnA & 1u) myc[mycap++] = ((unsigned long long)f2key(va.x) << 32) | (unsigned)(fa * 4 + 0);
                if (cnA & 2u) myc[mycap++] = ((unsigned long long)f2key(va.y) << 32) | (unsigned)(fa * 4 + 1);
                if (cnA & 4u) myc[mycap++] = ((unsigned long long)f2key(va.z) << 32) | (unsigned)(fa * 4 + 2);
                if (cnA & 8u) myc[mycap++] = ((unsigned long long)f2key(va.w) << 32) | (unsigned)(fa * 4 + 3);
                if (cnB & 1u) myc[mycap++] = ((unsigned long long)f2key(vb.x) << 32) | (unsigned)(fb * 4 + 0);
                if (cnB & 2u) myc[mycap++] = ((unsigned long long)f2key(vb.y) << 32) | (unsigned)(fb * 4 + 1);
                if (cnB & 4u) myc[mycap++] = ((unsigned long long)f2key(vb.z) << 32) | (unsigned)(fb * 4 + 2);
                if (cnB & 8u) myc[mycap++] = ((unsigned long long)f2key(vb.w) << 32) | (unsigned)(fb * 4 + 3);
            }
            if (cc == 3) {                              // group of 4 chunks complete
                mycnt += __popc(word);
                gbch[(i >> 2) * 1024 + tid] = word;
                word = 0;
            }
            __syncthreads();                            // all consumed stage s
            if (tid == 0 && i + 4 < NCHUNK) {
                mb_expect_tx(mb[s], CHUNK_F4 * 16);
                bulk_g2s(s2u(&buf[s * CHUNK_F4]), src + (size_t)(i + 4) * CHUNK_F4 * 16,
                         CHUNK_F4 * 16, mb[s]);
            }
        }
        // Block totals
        unsigned mc = (unsigned)mycap;
        #pragma unroll
        for (int off = 16; off; off >>= 1) {
            mycnt += __shfl_down_sync(0xffffffffu, mycnt, off);
            mc    += __shfl_down_sync(0xffffffffu, mc, off);
        }
        if (lane == 0) { atomicAdd(&aux[0], mycnt); atomicAdd(&aux[1], mc); }
        __syncthreads();
        cnt_hi = aux[0]; m = aux[1];
        if (k0) break;
        if ((cnt_hi < (unsigned)k && cnt_hi + m >= (unsigned)k) || attempt >= 1) break;
        lo_f = -INF; hi_f = INF;       // deterministic widen (count-check guarantee)
        __syncthreads();
    }

    // ---- exact threshold among candidates (11+11+10-bit radix), then fixups ----
    if (!k0) {
        unsigned r = (unsigned)k - cnt_hi;
        for (int i = tid; i < 2048; i += NT_) hist[i] = 0;
        __syncthreads();
        for (int i = 0; i < mycap; i++)
            atomicAdd(&hist[(unsigned)(myc[i] >> 32) >> 21], 1u);
        __syncthreads();
        block_find_bin(hist, 2048, r, sgrp, aux, tid, lane, w);
        unsigned bA = aux[0], rA = aux[1];
        __syncthreads();

        for (int i = tid; i < 2048; i += NT_) hist[i] = 0;
        __syncthreads();
        for (int i = 0; i < mycap; i++) {
            unsigned key = (unsigned)(myc[i] >> 32);
            if ((key >> 21) == bA) atomicAdd(&hist[(key >> 10) & 0x7FFu], 1u);
        }
        __syncthreads();
        block_find_bin(hist, 2048, rA, sgrp, aux, tid, lane, w);
        unsigned bB = aux[0], rB = aux[1];
        __syncthreads();

        for (int i = tid; i < 1024; i += NT_) hist[i] = 0;
        __syncthreads();
        for (int i = 0; i < mycap; i++) {
            unsigned key = (unsigned)(myc[i] >> 32);
            if ((key >> 21) == bA && ((key >> 10) & 0x7FFu) == bB)
                atomicAdd(&hist[key & 0x3FFu], 1u);
        }
        __syncthreads();
        block_find_bin(hist, 1024, rB, sgrp, aux, tid, lane, w);
        unsigned thrkey = (bA << 21) | (bB << 10) | aux[0];
        __syncthreads();

        for (int i = 0; i < mycap; i++) {
            unsigned long long cc2 = myc[i];
            if ((unsigned)(cc2 >> 32) > thrkey) {
                unsigned pos = (unsigned)cc2 & 0x3FFFFu;
                unsigned f4 = pos >> 2, e = pos & 3u;
                unsigned chn = f4 >> 11, rem = f4 & 2047u;
                unsigned h = rem >> 10, t = rem & 1023u;
                unsigned g = chn >> 2, cc = chn & 3u;
                atomicOr(&gbch[g * 1024 + t], 1u << (cc * 8 + h * 4 + e));
            }
        }
    }

    // ---- software grid barrier (144 resident CTAs; graph-replay safe) ----
    __threadfence();
    __syncthreads();
    if (tid == 0) {
        unsigned gen = *(volatile unsigned*)&g_bar_flag;
        unsigned t = atomicAdd(&g_bar_cnt, 1u);
        if (t == NCH_ - 1) {
            atomicExch(&g_bar_cnt, 0u);
            __threadfence();
            atomicAdd(&g_bar_flag, 1u);
        } else {
            while (*(volatile unsigned*)&g_bar_flag == gen) __nanosleep(64);
        }
        __threadfence();
    }
    __syncthreads();

    // ---- phase 2: per-thread OR of 9 channel words, apply to 8 float4s of x ----
    int gidx = blockIdx.x * NT_ + tid;               // 147456 threads, 131072 items
    if (gidx < N_ * 8192) {
        int nn = gidx >> 13;
        int wp = gidx & 8191;
        int g = wp >> 10, t = wp & 1023;
        const unsigned* bm = g_bitmap + (size_t)nn * C_ * 8192 + wp;
        unsigned wrd = 0;
        #pragma unroll
        for (int c = 0; c < C_; c++) wrd |= __ldg(bm + (size_t)c * 8192);
        const float4* xp = (const float4*)x + ((size_t)nn << 16);
        float4*       op = (float4*)out     + ((size_t)nn << 16);
        #pragma unroll
        for (int cc = 0; cc < 4; cc++) {
            #pragma unroll
            for (int h = 0; h < 2; h++) {
                int f4 = (g * 4 + cc) * 2048 + h * 1024 + t;
                unsigned nib = (wrd >> (cc * 8 + h * 4)) & 0xFu;
                float4 xv = xp[f4];
                float4 o;
                o.x = (nib & 1u) ? 0.0f : xv.x;
                o.y = (nib & 2u) ? 0.0f : xv.y;
                o.z = (nib & 4u) ? 0.0f : xv.z;
                o.w = (nib & 8u) ? 0.0f : xv.w;
                op[f4] = o;
            }
        }
    }
}

extern "C" void kernel_launch(void* const* d_in, const int* in_sizes, int n_in,
                              void* d_out, int out_size) {
    const float* inp   = (const float*)d_in[0];   // [16,9,512,512]
    const float* x     = (const float*)d_in[1];   // [16,1,512,512]
    const float* ratio = (const float*)d_in[2];   // [16]
    float* out = (float*)d_out;

    const int smem_bytes = STAGES * CHUNK_F4 * 16 + (2048 + 1024 + 4) * 4 + 32; // ~143.4KB
    cudaFuncSetAttribute(k_fused, cudaFuncAttributeMaxDynamicSharedMemorySize, smem_bytes);
    k_fused<<<NCH_, NT_, smem_bytes>>>(inp, ratio, x, out);
}